// round 3
// baseline (speedup 1.0000x reference)
#include <cuda_runtime.h>
#include <cuda_fp16.h>
#include <cstdint>
#include <cstddef>

#define DINL __device__ __forceinline__

static constexpr int BATCH = 64;
static constexpr int SEQ   = 512;
static constexpr int EMB   = 512;
static constexpr int HID   = 512;
static constexpr int G4    = 2048;      // 4*H
static constexpr int NTOK  = BATCH * SEQ; // 32768

// ---------------- device scratch (static: no runtime allocation) ----------------
// Permuted, transposed fp16 weights: 0=Wf, 1=Wb, 2=Uf, 3=Ub.
// Row r encodes: rb=r/64 (hidden-unit block), g=(r%64)/16 (gate i,f,g,o), jp=r%16; j=rb*16+jp
__device__ __align__(16) __half g_APERM[4][G4][EMB];       // 8 MB
__device__ __align__(16) __half g_X[(size_t)NTOK * EMB];   // gathered embeddings, row i=s*64+b, 32 MB
__device__ __align__(16) __half g_XW[2][G4][NTOK];         // xW^T per dir, 256 MB
__device__ __align__(16) __half g_H[2][2][BATCH * HID];    // h [parity][dir][b*512+j]
__device__ float g_BIAS[2][G4];
__device__ unsigned g_bar;

// ---------------- mma / ldmatrix helpers ----------------
DINL void ldsm_x4(uint32_t& r0, uint32_t& r1, uint32_t& r2, uint32_t& r3, uint32_t addr) {
    asm volatile("ldmatrix.sync.aligned.m8n8.x4.shared.b16 {%0,%1,%2,%3}, [%4];"
                 : "=r"(r0), "=r"(r1), "=r"(r2), "=r"(r3) : "r"(addr));
}
DINL void mma16816(float* d, uint32_t a0, uint32_t a1, uint32_t a2, uint32_t a3,
                   uint32_t b0, uint32_t b1) {
    asm volatile(
        "mma.sync.aligned.m16n8k16.row.col.f32.f16.f16.f32 "
        "{%0,%1,%2,%3}, {%4,%5,%6,%7}, {%8,%9}, {%0,%1,%2,%3};"
        : "+f"(d[0]), "+f"(d[1]), "+f"(d[2]), "+f"(d[3])
        : "r"(a0), "r"(a1), "r"(a2), "r"(a3), "r"(b0), "r"(b1));
}
DINL float sigf(float x) { return 1.0f / (1.0f + __expf(-x)); }

// ---------------- phase kernels ----------------
__global__ void init_kernel() {
    unsigned idx = blockIdx.x * blockDim.x + threadIdx.x;  // 32768 threads
    // zero parity-0 h buffers (both dirs): first 32768 uint32 of g_H
    reinterpret_cast<uint32_t*>(g_H)[idx] = 0u;
    if (idx == 0) g_bar = 0u;
}

__global__ void prep_w_kernel(const float* __restrict__ Wf, const float* __restrict__ Uf,
                              const float* __restrict__ bf, const float* __restrict__ Wb,
                              const float* __restrict__ Ub, const float* __restrict__ bb) {
    int m = blockIdx.x >> 11;       // 0..3
    int r = blockIdx.x & 2047;
    int rb = r >> 6, rem = r & 63, g = rem >> 4, jp = rem & 15;
    int col = g * 512 + rb * 16 + jp;
    const float* src = (m == 0) ? Wf : (m == 1) ? Wb : (m == 2) ? Uf : Ub;
    int e0 = threadIdx.x * 4;
#pragma unroll
    for (int q = 0; q < 4; q++) {
        int e = e0 + q;
        g_APERM[m][r][e] = __float2half(src[(size_t)e * G4 + col]);
    }
    if (m < 2 && threadIdx.x == 0) {
        const float* bsrc = m ? bb : bf;
        g_BIAS[m][r] = bsrc[col];
    }
}

__global__ void gather_x_kernel(const int* __restrict__ tokens, const float* __restrict__ emb) {
    int i = blockIdx.x;                 // token slot, i = s*64 + b
    int s = i >> 6, b = i & 63;
    int tok = tokens[b * SEQ + s];
    const float4* src = reinterpret_cast<const float4*>(emb + (size_t)tok * EMB);
    __half2* dst = reinterpret_cast<__half2*>(g_X + (size_t)i * EMB);
    float4 v = src[threadIdx.x];        // 128 threads x 4 floats = 512
    dst[threadIdx.x * 2]     = __floats2half2_rn(v.x, v.y);
    dst[threadIdx.x * 2 + 1] = __floats2half2_rn(v.z, v.w);
}

// ---------------- xW GEMM: g_XW[dir][r][i] = sum_e APERM[dir][r][e] * X[i][e] ----------------
__global__ void __launch_bounds__(256) xw_gemm_kernel() {
    __shared__ __half As[128 * 40];
    __shared__ __half Bs[128 * 40];
    int dir = blockIdx.z;
    int rbase = blockIdx.y * 128;
    int ibase = blockIdx.x * 128;
    int tid = threadIdx.x;
    int w = tid >> 5, lane = tid & 31;
    int wm = w & 3, wn = w >> 2;            // warp tile: rows 32, cols 64

    float acc[2][8][4];
#pragma unroll
    for (int a = 0; a < 2; a++)
#pragma unroll
        for (int b = 0; b < 8; b++)
#pragma unroll
            for (int c = 0; c < 4; c++) acc[a][b][c] = 0.0f;

    uint32_t as_base = (uint32_t)__cvta_generic_to_shared(As);
    uint32_t bs_base = (uint32_t)__cvta_generic_to_shared(Bs);
    const __half* gA = &g_APERM[dir][0][0];

    for (int kc = 0; kc < 16; kc++) {       // K=512 in chunks of 32
#pragma unroll
        for (int p = 0; p < 2; p++) {
            int ch = tid + p * 256;
            int row = ch >> 2, c = ch & 3;
            *(uint4*)&As[row * 40 + c * 8] =
                *(const uint4*)&gA[(size_t)(rbase + row) * EMB + kc * 32 + c * 8];
            *(uint4*)&Bs[row * 40 + c * 8] =
                *(const uint4*)&g_X[(size_t)(ibase + row) * EMB + kc * 32 + c * 8];
        }
        __syncthreads();
#pragma unroll
        for (int kk = 0; kk < 2; kk++) {
            uint32_t a[2][4];
#pragma unroll
            for (int mt = 0; mt < 2; mt++) {
                int rr = wm * 32 + mt * 16 + (lane & 15);
                int cc = kk * 16 + ((lane >> 4) & 1) * 8;
                ldsm_x4(a[mt][0], a[mt][1], a[mt][2], a[mt][3],
                        as_base + (uint32_t)(rr * 40 + cc) * 2);
            }
            uint32_t bf[8][2];
#pragma unroll
            for (int bp = 0; bp < 4; bp++) {
                int n0 = wn * 64 + bp * 16;
                int rr = n0 + ((lane >> 4) << 3) + (lane & 7);
                int cc = kk * 16 + ((lane >> 3) & 1) * 8;
                ldsm_x4(bf[bp * 2][0], bf[bp * 2][1], bf[bp * 2 + 1][0], bf[bp * 2 + 1][1],
                        bs_base + (uint32_t)(rr * 40 + cc) * 2);
            }
#pragma unroll
            for (int mt = 0; mt < 2; mt++)
#pragma unroll
                for (int nt = 0; nt < 8; nt++)
                    mma16816(acc[mt][nt], a[mt][0], a[mt][1], a[mt][2], a[mt][3],
                             bf[nt][0], bf[nt][1]);
        }
        __syncthreads();
    }
#pragma unroll
    for (int mt = 0; mt < 2; mt++)
#pragma unroll
        for (int nt = 0; nt < 8; nt++) {
            int row = rbase + wm * 32 + mt * 16 + (lane >> 2);
            int col = ibase + wn * 64 + nt * 8 + (lane & 3) * 2;
            *(__half2*)&g_XW[dir][row][col]     = __floats2half2_rn(acc[mt][nt][0], acc[mt][nt][1]);
            *(__half2*)&g_XW[dir][row + 8][col] = __floats2half2_rn(acc[mt][nt][2], acc[mt][nt][3]);
        }
}

// ---------------- persistent recurrence kernel ----------------
// 64 CTAs = 2 dirs x 32 blocks of 64 gate-rows (16 hidden units x 4 gates).
// SMEM: U slice (resident), h (reloaded per step), z exchange, bias.
static constexpr int US_STRIDE = 520;   // halves, pad for conflict-free ldmatrix
static constexpr int ZS_STRIDE = 72;    // floats
static constexpr int SMEM_BYTES = 2 * 64 * US_STRIDE * 2 + 64 * ZS_STRIDE * 4 + 64 * 4;

__global__ void __launch_bounds__(256) recur_kernel(float* __restrict__ out) {
    extern __shared__ __half smem_dyn[];
    __half* Us = smem_dyn;                               // 64 x 520
    __half* hs = smem_dyn + 64 * US_STRIDE;              // 64 x 520
    float*  zs = (float*)(smem_dyn + 2 * 64 * US_STRIDE);// 64 x 72
    float*  bsm = zs + 64 * ZS_STRIDE;                   // 64

    int cta = blockIdx.x;
    int dir = cta >> 5, rb = cta & 31;
    int rbase = rb * 64;
    int tid = threadIdx.x, w = tid >> 5, lane = tid & 31;
    int wm = w >> 1, wn = w & 1;    // wm = gate tile (16 rows), wn = batch half (32)

    // load resident U slice
#pragma unroll
    for (int p = 0; p < 16; p++) {
        int ch = tid + p * 256;
        int row = ch >> 6, c = ch & 63;
        *(uint4*)&Us[row * US_STRIDE + c * 8] =
            *(const uint4*)&g_APERM[2 + dir][rbase + row][c * 8];
    }
    if (tid < 64) bsm[tid] = g_BIAS[dir][rbase + tid];

    float creg[4] = {0.f, 0.f, 0.f, 0.f};
    int eb = tid >> 2;            // batch 0..63
    int jq = (tid & 3) * 4;       // j' base (4 hidden units per thread)

    uint32_t us_base = (uint32_t)__cvta_generic_to_shared(Us);
    uint32_t hs_base = (uint32_t)__cvta_generic_to_shared(hs);
    __syncthreads();

    for (int t = 0; t < SEQ; t++) {
        int par = t & 1;
        const __half* hsrc = &g_H[par][dir][0];
#pragma unroll
        for (int p = 0; p < 16; p++) {
            int ch = tid + p * 256;
            int row = ch >> 6, c = ch & 63;
            *(uint4*)&hs[row * US_STRIDE + c * 8] =
                *(const uint4*)&hsrc[row * HID + c * 8];
        }
        __syncthreads();

        float acc[4][4];
#pragma unroll
        for (int a = 0; a < 4; a++)
#pragma unroll
            for (int c = 0; c < 4; c++) acc[a][c] = 0.0f;

#pragma unroll 4
        for (int kk = 0; kk < 32; kk++) {
            uint32_t a0, a1, a2, a3;
            {
                int rr = wm * 16 + (lane & 15);
                int cc = kk * 16 + ((lane >> 4) & 1) * 8;
                ldsm_x4(a0, a1, a2, a3, us_base + (uint32_t)(rr * US_STRIDE + cc) * 2);
            }
            uint32_t bf[4][2];
#pragma unroll
            for (int bp = 0; bp < 2; bp++) {
                int n0 = wn * 32 + bp * 16;
                int rr = n0 + ((lane >> 4) << 3) + (lane & 7);
                int cc = kk * 16 + ((lane >> 3) & 1) * 8;
                ldsm_x4(bf[bp * 2][0], bf[bp * 2][1], bf[bp * 2 + 1][0], bf[bp * 2 + 1][1],
                        hs_base + (uint32_t)(rr * US_STRIDE + cc) * 2);
            }
#pragma unroll
            for (int nt = 0; nt < 4; nt++)
                mma16816(acc[nt], a0, a1, a2, a3, bf[nt][0], bf[nt][1]);
        }
        // write z tile to SMEM for gate exchange
#pragma unroll
        for (int nt = 0; nt < 4; nt++) {
            int row = wm * 16 + (lane >> 2);
            int col = wn * 32 + nt * 8 + (lane & 3) * 2;
            *(float2*)&zs[row * ZS_STRIDE + col]       = make_float2(acc[nt][0], acc[nt][1]);
            *(float2*)&zs[(row + 8) * ZS_STRIDE + col] = make_float2(acc[nt][2], acc[nt][3]);
        }
        __syncthreads();

        // epilogue: each thread owns (batch eb, hidden units jq..jq+3)
        int sx = dir ? (SEQ - 1 - t) : t;   // sequence position consumed AND emitted
        const __half* xwp = &g_XW[dir][0][0];
        float hv[4];
#pragma unroll
        for (int q = 0; q < 4; q++) {
            int jp = jq + q;
            float z[4];
#pragma unroll
            for (int g = 0; g < 4; g++) {
                int rl = g * 16 + jp;
                z[g] = zs[rl * ZS_STRIDE + eb]
                     + __half2float(xwp[(size_t)(rbase + rl) * NTOK + sx * 64 + eb])
                     + bsm[rl];
            }
            float ig = sigf(z[0]);
            float fg = sigf(z[1]);
            float gg = tanhf(z[2]);
            float og = sigf(z[3]);
            creg[q] = fg * creg[q] + ig * gg;
            hv[q] = og * tanhf(creg[q]);
        }
        // write h (fp16, next parity) and output (fp32)
        __half* hdst = &g_H[par ^ 1][dir][eb * HID + rb * 16 + jq];
        *(__half2*)&hdst[0] = __floats2half2_rn(hv[0], hv[1]);
        *(__half2*)&hdst[2] = __floats2half2_rn(hv[2], hv[3]);
        *(float4*)&out[(size_t)eb * (SEQ * 1024) + (size_t)sx * 1024 + dir * 512 + rb * 16 + jq] =
            make_float4(hv[0], hv[1], hv[2], hv[3]);

        // grid barrier (64 co-resident CTAs)
        __threadfence();
        __syncthreads();
        if (tid == 0) {
            atomicAdd(&g_bar, 1u);
            unsigned target = 64u * (unsigned)(t + 1);
            while (*(volatile unsigned*)&g_bar < target) { }
            __threadfence();
        }
        __syncthreads();
    }
}

// ---------------- launch ----------------
extern "C" void kernel_launch(void* const* d_in, const int* in_sizes, int n_in,
                              void* d_out, int out_size) {
    const int*   tokens = (const int*)d_in[0];
    const float* emb    = (const float*)d_in[1];
    const float* Wf     = (const float*)d_in[2];
    const float* Uf     = (const float*)d_in[3];
    const float* bf     = (const float*)d_in[4];
    const float* Wb     = (const float*)d_in[5];
    const float* Ub     = (const float*)d_in[6];
    const float* bb     = (const float*)d_in[7];
    float* out = (float*)d_out;

    cudaFuncSetAttribute(recur_kernel, cudaFuncAttributeMaxDynamicSharedMemorySize, SMEM_BYTES);

    init_kernel<<<128, 256>>>();
    prep_w_kernel<<<8192, 128>>>(Wf, Uf, bf, Wb, Ub, bb);
    gather_x_kernel<<<NTOK, 128>>>(tokens, emb);
    dim3 gg(256, 16, 2);
    xw_gemm_kernel<<<gg, 256>>>();
    recur_kernel<<<64, 256, SMEM_BYTES>>>(out);
}

// round 6
// speedup vs baseline: 1.7955x; 1.7955x over previous
#include <cuda_runtime.h>
#include <cuda_fp16.h>
#include <cstdint>
#include <cstddef>

#define DINL __device__ __forceinline__

static constexpr int BATCH = 64;
static constexpr int SEQ   = 512;
static constexpr int EMB   = 512;
static constexpr int HID   = 512;
static constexpr int G4    = 2048;
static constexpr int NTOK  = BATCH * SEQ;

// Permuted fp16 weights: 0=Wf,1=Wb,2=Uf,3=Ub.
// Row r: rblk=r>>5, lr=r&31, g=lr>>3, jp=lr&7  <->  original column g*512 + rblk*8 + jp
__device__ __align__(16) __half g_APERM[4][G4][EMB];
__device__ __align__(16) __half g_X[(size_t)NTOK * EMB];
__device__ __align__(16) __half g_XW[2][G4][NTOK];
__device__ __align__(16) __half g_H[2][2][BATCH * HID];
__device__ float g_BIAS[2][G4];
__device__ unsigned g_bar;

// ---------------- helpers ----------------
DINL void ldsm_x4(uint32_t& r0, uint32_t& r1, uint32_t& r2, uint32_t& r3, uint32_t addr) {
    asm volatile("ldmatrix.sync.aligned.m8n8.x4.shared.b16 {%0,%1,%2,%3}, [%4];"
                 : "=r"(r0), "=r"(r1), "=r"(r2), "=r"(r3) : "r"(addr));
}
DINL void mma16816(float* d, uint32_t a0, uint32_t a1, uint32_t a2, uint32_t a3,
                   uint32_t b0, uint32_t b1) {
    asm volatile("mma.sync.aligned.m16n8k16.row.col.f32.f16.f16.f32 "
                 "{%0,%1,%2,%3}, {%4,%5,%6,%7}, {%8,%9}, {%0,%1,%2,%3};"
                 : "+f"(d[0]), "+f"(d[1]), "+f"(d[2]), "+f"(d[3])
                 : "r"(a0), "r"(a1), "r"(a2), "r"(a3), "r"(b0), "r"(b1));
}
DINL float sigf(float x) { return 1.0f / (1.0f + __expf(-x)); }
DINL uint32_t pack_h2(float a, float b) {
    return ((uint32_t)__half_as_ushort(__float2half_rn(b)) << 16) |
           (uint32_t)__half_as_ushort(__float2half_rn(a));
}
DINL uint4 ldg_cg(const void* p) {
    uint4 v;
    asm volatile("ld.global.cg.v4.u32 {%0,%1,%2,%3}, [%4];"
                 : "=r"(v.x), "=r"(v.y), "=r"(v.z), "=r"(v.w) : "l"(p));
    return v;
}
DINL void stg_cg32(void* p, uint32_t v) {
    asm volatile("st.global.cg.u32 [%0], %1;" :: "l"(p), "r"(v) : "memory");
}

// ---------------- phase kernels ----------------
__global__ void init_kernel() {
    unsigned idx = blockIdx.x * blockDim.x + threadIdx.x;
    reinterpret_cast<uint32_t*>(g_H)[idx] = 0u;   // zero parity-0 h, both dirs
    if (idx == 0) g_bar = 0u;
}

__global__ void prep_w_kernel(const float* __restrict__ Wf, const float* __restrict__ Uf,
                              const float* __restrict__ bf, const float* __restrict__ Wb,
                              const float* __restrict__ Ub, const float* __restrict__ bb) {
    int m = blockIdx.x >> 11;
    int r = blockIdx.x & 2047;
    int rblk = r >> 5, lr = r & 31, g = lr >> 3, jp = lr & 7;
    int col = g * 512 + rblk * 8 + jp;
    const float* src = (m == 0) ? Wf : (m == 1) ? Wb : (m == 2) ? Uf : Ub;
    int e0 = threadIdx.x * 4;
#pragma unroll
    for (int q = 0; q < 4; q++)
        g_APERM[m][r][e0 + q] = __float2half(src[(size_t)(e0 + q) * G4 + col]);
    if (m < 2 && threadIdx.x == 0) g_BIAS[m][r] = (m ? bb : bf)[col];
}

__global__ void gather_x_kernel(const int* __restrict__ tokens, const float* __restrict__ emb) {
    int i = blockIdx.x;
    int s = i >> 6, b = i & 63;
    int tok = tokens[b * SEQ + s];
    float4 v = reinterpret_cast<const float4*>(emb + (size_t)tok * EMB)[threadIdx.x];
    __half2* dst = reinterpret_cast<__half2*>(g_X + (size_t)i * EMB);
    dst[threadIdx.x * 2]     = __floats2half2_rn(v.x, v.y);
    dst[threadIdx.x * 2 + 1] = __floats2half2_rn(v.z, v.w);
}

// ---------------- xW GEMM (HMMA) ----------------
__global__ void __launch_bounds__(256) xw_gemm_kernel() {
    __shared__ __half As[128 * 40];
    __shared__ __half Bs[128 * 40];
    int dir = blockIdx.z, rbase = blockIdx.y * 128, ibase = blockIdx.x * 128;
    int tid = threadIdx.x, w = tid >> 5, lane = tid & 31;
    int wm = w & 3, wn = w >> 2;
    float acc[2][8][4];
#pragma unroll
    for (int a = 0; a < 2; a++)
#pragma unroll
        for (int b = 0; b < 8; b++)
#pragma unroll
            for (int c = 0; c < 4; c++) acc[a][b][c] = 0.0f;
    uint32_t as_base = (uint32_t)__cvta_generic_to_shared(As);
    uint32_t bs_base = (uint32_t)__cvta_generic_to_shared(Bs);
    const __half* gA = &g_APERM[dir][0][0];
    for (int kc = 0; kc < 16; kc++) {
#pragma unroll
        for (int p = 0; p < 2; p++) {
            int ch = tid + p * 256, row = ch >> 2, c = ch & 3;
            *(uint4*)&As[row * 40 + c * 8] =
                *(const uint4*)&gA[(size_t)(rbase + row) * EMB + kc * 32 + c * 8];
            *(uint4*)&Bs[row * 40 + c * 8] =
                *(const uint4*)&g_X[(size_t)(ibase + row) * EMB + kc * 32 + c * 8];
        }
        __syncthreads();
#pragma unroll
        for (int kk = 0; kk < 2; kk++) {
            uint32_t a[2][4];
#pragma unroll
            for (int mt = 0; mt < 2; mt++) {
                int rr = wm * 32 + mt * 16 + (lane & 15);
                int cc = kk * 16 + ((lane >> 4) & 1) * 8;
                ldsm_x4(a[mt][0], a[mt][1], a[mt][2], a[mt][3],
                        as_base + (uint32_t)(rr * 40 + cc) * 2);
            }
            uint32_t bq[8][2];
#pragma unroll
            for (int bp = 0; bp < 4; bp++) {
                int rr = wn * 64 + bp * 16 + ((lane >> 4) << 3) + (lane & 7);
                int cc = kk * 16 + ((lane >> 3) & 1) * 8;
                ldsm_x4(bq[bp * 2][0], bq[bp * 2][1], bq[bp * 2 + 1][0], bq[bp * 2 + 1][1],
                        bs_base + (uint32_t)(rr * 40 + cc) * 2);
            }
#pragma unroll
            for (int mt = 0; mt < 2; mt++)
#pragma unroll
                for (int nt = 0; nt < 8; nt++)
                    mma16816(acc[mt][nt], a[mt][0], a[mt][1], a[mt][2], a[mt][3],
                             bq[nt][0], bq[nt][1]);
        }
        __syncthreads();
    }
#pragma unroll
    for (int mt = 0; mt < 2; mt++)
#pragma unroll
        for (int nt = 0; nt < 8; nt++) {
            int row = rbase + wm * 32 + mt * 16 + (lane >> 2);
            int col = ibase + wn * 64 + nt * 8 + (lane & 3) * 2;
            *(__half2*)&g_XW[dir][row][col]     = __floats2half2_rn(acc[mt][nt][0], acc[mt][nt][1]);
            *(__half2*)&g_XW[dir][row + 8][col] = __floats2half2_rn(acc[mt][nt][2], acc[mt][nt][3]);
        }
}

// ---------------- persistent recurrence: U weights register-resident ----------------
// 128 CTAs = 2 dirs x 64 blocks of 32 gate rows (4 gates x 8 hidden units).
// Warp layout: mt = w>>2 (m16 tile), nq = w&3 (batch 16-quarter).
static constexpr int HS_STRIDE = 520;   // halves
static constexpr int XS_STRIDE = 72;    // halves
static constexpr int ZS_STRIDE = 68;    // floats
static constexpr int SO_H  = 0;                        // 64 x 520 x 2 = 66560
static constexpr int SO_XW = 66560;                    // 32 x 72 x 2  = 4608
static constexpr int SO_Z  = 71168;                    // 32 x 68 x 4  = 8704
static constexpr int SO_B  = 79872;                    // 32 x 4
static constexpr int SMEM_SZ = 80000;

__global__ void __launch_bounds__(256, 1) recur_kernel(float* __restrict__ out) {
    extern __shared__ char smem[];
    __half* hs = (__half*)(smem + SO_H);
    __half* xs = (__half*)(smem + SO_XW);
    float*  zs = (float*)(smem + SO_Z);
    float*  bsm = (float*)(smem + SO_B);

    int cta = blockIdx.x;
    int dir = cta >> 6, rblk = cta & 63;
    int rbase = rblk * 32;
    int tid = threadIdx.x, w = tid >> 5, lane = tid & 31;
    int mt = w >> 2, nq = w & 3;
    uint32_t hs_base = (uint32_t)__cvta_generic_to_shared(hs);

    // ---- stage U (32 rows x 512) into hs region, ldsm A-fragments into registers ----
#pragma unroll
    for (int p = 0; p < 8; p++) {
        int idx = tid + p * 256;            // 2048 uint4
        int row = idx >> 6, c = idx & 63;
        *(uint4*)&hs[row * HS_STRIDE + c * 8] =
            *(const uint4*)&g_APERM[2 + dir][rbase + row][c * 8];
    }
    if (tid < 32) bsm[tid] = g_BIAS[dir][rbase + tid];
    __syncthreads();

    uint32_t a[32][4];
#pragma unroll
    for (int kk = 0; kk < 32; kk++) {
        int rr = mt * 16 + (lane & 15);
        int cc = kk * 16 + ((lane >> 4) & 1) * 8;
        ldsm_x4(a[kk][0], a[kk][1], a[kk][2], a[kk][3],
                hs_base + (uint32_t)(rr * HS_STRIDE + cc) * 2);
    }
    __syncthreads();

    float creg[2] = {0.f, 0.f};
    int eb = tid & 63;          // batch
    int hq = tid >> 6;          // hidden pair index (0..3), jp = hq*2 + q

    for (int t = 0; t < SEQ; t++) {
        int par = t & 1;
        int sx = dir ? (SEQ - 1 - t) : t;

        // XW tile: 32 rows x 64 halves, coalesced
        {
            int row = tid >> 3, c = tid & 7;
            *(uint4*)&xs[row * XS_STRIDE + c * 8] =
                *(const uint4*)&g_XW[dir][rbase + row][sx * 64 + c * 8];
        }
        // h: 64 batch rows x 512 halves, L1-bypass
        const __half* hsrc = &g_H[par][dir][0];
#pragma unroll
        for (int p = 0; p < 16; p++) {
            int idx = tid + p * 256;        // 4096 uint4
            int row = idx >> 6, c = idx & 63;
            *(uint4*)&hs[row * HS_STRIDE + c * 8] = ldg_cg(&hsrc[row * HID + c * 8]);
        }
        __syncthreads();

        float acc[2][4];
#pragma unroll
        for (int i = 0; i < 2; i++)
#pragma unroll
            for (int c = 0; c < 4; c++) acc[i][c] = 0.0f;

#pragma unroll
        for (int kk = 0; kk < 32; kk++) {
            uint32_t b0, b1, b2, b3;
            int rr = nq * 16 + ((lane >> 4) << 3) + (lane & 7);
            int cc = kk * 16 + ((lane >> 3) & 1) * 8;
            ldsm_x4(b0, b1, b2, b3, hs_base + (uint32_t)(rr * HS_STRIDE + cc) * 2);
            mma16816(acc[0], a[kk][0], a[kk][1], a[kk][2], a[kk][3], b0, b1);
            mma16816(acc[1], a[kk][0], a[kk][1], a[kk][2], a[kk][3], b2, b3);
        }
        // z -> SMEM exchange
#pragma unroll
        for (int i = 0; i < 2; i++) {
            int row = mt * 16 + (lane >> 2);
            int col = nq * 16 + i * 8 + (lane & 3) * 2;
            *(float2*)&zs[row * ZS_STRIDE + col]       = make_float2(acc[i][0], acc[i][1]);
            *(float2*)&zs[(row + 8) * ZS_STRIDE + col] = make_float2(acc[i][2], acc[i][3]);
        }
        __syncthreads();

        // cell update: thread owns (batch eb, hidden units hq*2, hq*2+1)
        float hv[2];
#pragma unroll
        for (int q = 0; q < 2; q++) {
            int jp = hq * 2 + q;
            float z0 = zs[jp * ZS_STRIDE + eb]        + __half2float(xs[jp * XS_STRIDE + eb])        + bsm[jp];
            float z1 = zs[(8 + jp) * ZS_STRIDE + eb]  + __half2float(xs[(8 + jp) * XS_STRIDE + eb])  + bsm[8 + jp];
            float z2 = zs[(16 + jp) * ZS_STRIDE + eb] + __half2float(xs[(16 + jp) * XS_STRIDE + eb]) + bsm[16 + jp];
            float z3 = zs[(24 + jp) * ZS_STRIDE + eb] + __half2float(xs[(24 + jp) * XS_STRIDE + eb]) + bsm[24 + jp];
            float ig = sigf(z0), fg = sigf(z1), gg = tanhf(z2), og = sigf(z3);
            creg[q] = fg * creg[q] + ig * gg;
            hv[q] = og * tanhf(creg[q]);
        }
        stg_cg32(&g_H[par ^ 1][dir][eb * HID + rblk * 8 + hq * 2], pack_h2(hv[0], hv[1]));
        *(float2*)&out[((size_t)eb * SEQ + sx) * 1024 + dir * 512 + rblk * 8 + hq * 2] =
            make_float2(hv[0], hv[1]);

        // grid barrier (128 co-resident CTAs)
        __syncthreads();
        if (tid == 0) {
            unsigned tgt = 128u * (unsigned)(t + 1), v;
            asm volatile("membar.gl;" ::: "memory");
            asm volatile("red.global.gpu.add.u32 [%0], %1;" :: "l"(&g_bar), "r"(1u) : "memory");
            do {
                asm volatile("ld.global.acquire.gpu.u32 %0, [%1];" : "=r"(v) : "l"(&g_bar));
            } while (v < tgt);
        }
        __syncthreads();
    }
}

// ---------------- launch ----------------
extern "C" void kernel_launch(void* const* d_in, const int* in_sizes, int n_in,
                              void* d_out, int out_size) {
    const int*   tokens = (const int*)d_in[0];
    const float* emb    = (const float*)d_in[1];
    const float* Wf     = (const float*)d_in[2];
    const float* Uf     = (const float*)d_in[3];
    const float* bf     = (const float*)d_in[4];
    const float* Wb     = (const float*)d_in[5];
    const float* Ub     = (const float*)d_in[6];
    const float* bb     = (const float*)d_in[7];
    float* out = (float*)d_out;

    cudaFuncSetAttribute(recur_kernel, cudaFuncAttributeMaxDynamicSharedMemorySize, SMEM_SZ);

    init_kernel<<<128, 256>>>();
    prep_w_kernel<<<8192, 128>>>(Wf, Uf, bf, Wb, Ub, bb);
    gather_x_kernel<<<NTOK, 128>>>(tokens, emb);
    dim3 gg(256, 16, 2);
    xw_gemm_kernel<<<gg, 256>>>();
    recur_kernel<<<128, 256, SMEM_SZ>>>(out);
}